// round 8
// baseline (speedup 1.0000x reference)
#include <cuda_runtime.h>
#include <cuda_fp16.h>
#include <mma.h>
#include <cstdint>

using namespace nvcuda;

#define N_TOK 16384
#define DIN   512
#define DOUT  512
#define NEXP  16

#define BM 128
#define BN 128
#define BK 32
#define NIT (DIN / BK)   // 16
#define NSTAGE 4

// ---------------- device scratch (no allocations allowed) ----------------
__device__ int    g_cnt[NEXP];
__device__ int    g_perm[NEXP * N_TOK];
__device__ float  g_pw  [NEXP * N_TOK];
__device__ __half g_xh [N_TOK * DIN];          // fp16 copy of x
__device__ __half g_ewh[NEXP * DIN * DOUT];    // fp16 copy of expert_w (same layout)

// ---------------- fused prep: zero-out | convert ew | convert x | router --
// block roles: [0,256) zero out; [256,768) convert ew; [768,1024) convert x;
//              [1024,1280) router (g_cnt pre-zeroed by host memset).
__global__ void __launch_bounds__(256)
prep_kernel(const float* __restrict__ x,
            const float* __restrict__ ew,
            const float* __restrict__ gw,   // [DIN, NEXP]
            const float* __restrict__ gb,   // [NEXP]
            float* __restrict__ out) {
    __shared__ float sgwT[NEXP * DIN];      // used by router blocks only (32KB)
    int bx = blockIdx.x, tid = threadIdx.x;

    if (bx < 256) {
        // zero the output (2M float4)
        float4 z = make_float4(0.f, 0.f, 0.f, 0.f);
        float4* o4 = (float4*)out;
        for (int i = bx * 256 + tid; i < N_TOK * DOUT / 4; i += 256 * 256)
            o4[i] = z;
    } else if (bx < 768) {
        // convert expert_w (2M float4)
        int b = bx - 256;
        for (int i = b * 256 + tid; i < NEXP * DIN * DOUT / 4; i += 512 * 256) {
            float4 v = ((const float4*)ew)[i];
            __half2* d2 = (__half2*)(g_ewh + (size_t)i * 4);
            d2[0] = __floats2half2_rn(v.x, v.y);
            d2[1] = __floats2half2_rn(v.z, v.w);
        }
    } else if (bx < 1024) {
        // convert x (2M float4)
        int b = bx - 768;
        for (int i = b * 256 + tid; i < N_TOK * DIN / 4; i += 256 * 256) {
            float4 v = ((const float4*)x)[i];
            __half2* d2 = (__half2*)(g_xh + (size_t)i * 4);
            d2[0] = __floats2half2_rn(v.x, v.y);
            d2[1] = __floats2half2_rn(v.z, v.w);
        }
    } else {
        // router: 64 tokens per block
        int rb = bx - 1024;
        for (int i = tid; i < NEXP * DIN; i += 256) {
            int e = i / DIN, k = i % DIN;
            sgwT[i] = gw[k * NEXP + e];
        }
        __syncthreads();

        int warp = tid >> 5, lane = tid & 31;
        int base_tok = (rb * 8 + warp) * 8;
        for (int t = 0; t < 8; t++) {
            int tok = base_tok + t;
            float acc[NEXP];
#pragma unroll
            for (int e = 0; e < NEXP; e++) acc[e] = 0.f;
            const float* xr = x + (size_t)tok * DIN;
            for (int k = lane; k < DIN; k += 32) {
                float xv = xr[k];
#pragma unroll
                for (int e = 0; e < NEXP; e++)
                    acc[e] = fmaf(xv, sgwT[e * DIN + k], acc[e]);
            }
#pragma unroll
            for (int off = 16; off >= 1; off >>= 1) {
#pragma unroll
                for (int e = 0; e < NEXP; e++)
                    acc[e] += __shfl_xor_sync(0xffffffffu, acc[e], off);
            }
            if (lane == 0) {
                float b1 = -1e30f, b2 = -1e30f; int i1 = 0, i2 = 0;
#pragma unroll
                for (int e = 0; e < NEXP; e++) {
                    float v = acc[e] + gb[e];
                    if (v > b1)      { b2 = b1; i2 = i1; b1 = v; i1 = e; }
                    else if (v > b2) { b2 = v;  i2 = e; }
                }
                float ex  = expf(b2 - b1);
                float inv = 1.f / (1.f + ex);
                int p = atomicAdd(&g_cnt[i1], 1);
                g_perm[i1 * N_TOK + p] = tok;  g_pw[i1 * N_TOK + p] = inv;
                p = atomicAdd(&g_cnt[i2], 1);
                g_perm[i2 * N_TOK + p] = tok;  g_pw[i2 * N_TOK + p] = ex * inv;
            }
        }
    }
}

// ---------------- cp.async helpers ---------------------------------------
__device__ __forceinline__ void cp_async16(void* smem_dst, const void* gmem_src) {
    unsigned int s = (unsigned int)__cvta_generic_to_shared(smem_dst);
    asm volatile("cp.async.cg.shared.global [%0], [%1], 16;\n" :: "r"(s), "l"(gmem_src));
}
__device__ __forceinline__ void cp_commit() { asm volatile("cp.async.commit_group;\n"); }
__device__ __forceinline__ void cp_wait2()  { asm volatile("cp.async.wait_group 2;\n"); }
__device__ __forceinline__ void cp_wait1()  { asm volatile("cp.async.wait_group 1;\n"); }
__device__ __forceinline__ void cp_wait0()  { asm volatile("cp.async.wait_group 0;\n"); }

// ---------------- grouped expert GEMM: fp16 HMMA, fp32 accum, 4-stage ----
// grid = (DOUT/BN, N_TOK/BM, NEXP); block = 256 threads (8 warps).
// dynamic smem layout:
//   sA: NSTAGE * 128 * 40 halves  = 40960 B   @ 0       (reused as epilogue f32 buf)
//   sB: NSTAGE * 32 * 136 halves  = 34816 B   @ 40960
//   s_tok: 512 B @ 75776 ; s_w: 512 B @ 76288 ; total 76800 B
#define SM_B_OFF   40960
#define SM_TOK_OFF 75776
#define SM_W_OFF   76288
#define SMEM_BYTES 76800
#define LDA 40
#define LDB 136

__global__ void __launch_bounds__(256, 2)
moe_gemm_kernel(const float* __restrict__ eb,   // [E, DOUT]
                float* __restrict__ out) {
    extern __shared__ char smem[];
    int e  = blockIdx.z;
    int me = g_cnt[e];
    int m0 = blockIdx.y * BM;
    if (m0 >= me) return;
    int n0 = blockIdx.x * BN;

    __half* sA   = (__half*)smem;                       // [NSTAGE][128][LDA]
    __half* sB   = (__half*)(smem + SM_B_OFF);          // [NSTAGE][32][LDB]
    int*    s_tok = (int*)(smem + SM_TOK_OFF);
    float*  s_w   = (float*)(smem + SM_W_OFF);
    float*  s_epi = (float*)smem;                       // epilogue alias of sA

    int tid = threadIdx.x;
    for (int i = tid; i < BM; i += 256) {
        int m = m0 + i;
        if (m < me) { s_tok[i] = g_perm[e * N_TOK + m]; s_w[i] = g_pw[e * N_TOK + m]; }
        else        { s_tok[i] = 0;                     s_w[i] = 0.f; }
    }
    __syncthreads();

    const __half* wpt = g_ewh + (size_t)e * DIN * DOUT + n0;

    auto prefetch = [&](int it, int st) {
        int k0 = it * BK;
        __half* a = sA + (size_t)st * 128 * LDA;
        __half* b = sB + (size_t)st * 32 * LDB;
#pragma unroll
        for (int i = 0; i < 2; i++) {           // A: 128 rows x 4 chunks
            int idx = tid + i * 256;
            int row = idx >> 2, c = idx & 3;
            cp_async16(a + row * LDA + c * 8,
                       g_xh + (size_t)s_tok[row] * DIN + k0 + c * 8);
        }
#pragma unroll
        for (int i = 0; i < 2; i++) {           // B: 32 rows x 16 chunks
            int idx = tid + i * 256;
            int kk = idx >> 4, c = idx & 15;
            cp_async16(b + kk * LDB + c * 8,
                       wpt + (size_t)(k0 + kk) * DOUT + c * 8);
        }
    };

    int warp = tid >> 5, lane = tid & 31;
    int wm = (warp >> 2) * 64;   // 2 warp-rows of 64
    int wn = (warp & 3) * 32;    // 4 warp-cols of 32

    wmma::fragment<wmma::accumulator, 16, 16, 16, float> accf[4][2];
#pragma unroll
    for (int i = 0; i < 4; i++)
#pragma unroll
        for (int j = 0; j < 2; j++) wmma::fill_fragment(accf[i][j], 0.f);

    prefetch(0, 0); cp_commit();
    prefetch(1, 1); cp_commit();
    prefetch(2, 2); cp_commit();

    for (int it = 0; it < NIT; it++) {
        int st = it & (NSTAGE - 1);
        if (it < NIT - 2)      cp_wait2();
        else if (it == NIT - 2) cp_wait1();
        else                    cp_wait0();
        __syncthreads();        // stage `st` resident

        if (it + 3 < NIT) { prefetch(it + 3, (it + 3) & (NSTAGE - 1)); cp_commit(); }

        const __half* a = sA + (size_t)st * 128 * LDA;
        const __half* b = sB + (size_t)st * 32 * LDB;
#pragma unroll
        for (int kk = 0; kk < BK; kk += 16) {
            wmma::fragment<wmma::matrix_a, 16, 16, 16, __half, wmma::row_major> af[4];
            wmma::fragment<wmma::matrix_b, 16, 16, 16, __half, wmma::row_major> bf[2];
#pragma unroll
            for (int i = 0; i < 4; i++)
                wmma::load_matrix_sync(af[i], a + (wm + i * 16) * LDA + kk, LDA);
#pragma unroll
            for (int j = 0; j < 2; j++)
                wmma::load_matrix_sync(bf[j], b + kk * LDB + wn + j * 16, LDB);
#pragma unroll
            for (int i = 0; i < 4; i++)
#pragma unroll
                for (int j = 0; j < 2; j++)
                    wmma::mma_sync(accf[i][j], af[i], bf[j], accf[i][j]);
        }
    }

    // ---- epilogue: out[token, n] += w * (acc + bias); s_epi aliases sA ----
    __syncthreads();
    const float* bias = eb + (size_t)e * DOUT + n0;
    float* warp_buf = s_epi + warp * 16 * 20;   // 8 warps x 16x20 f32 = 10240 B < 40960
#pragma unroll
    for (int i = 0; i < 4; i++) {
#pragma unroll
        for (int j = 0; j < 2; j++) {
            wmma::store_matrix_sync(warp_buf, accf[i][j], 20, wmma::mem_row_major);
            __syncwarp();
#pragma unroll
            for (int t = lane; t < 256; t += 32) {
                int r = t >> 4, c = t & 15;
                int row = wm + i * 16 + r;
                int col = wn + j * 16 + c;
                float w = s_w[row];
                if (w != 0.f) {
                    float v = w * (warp_buf[r * 20 + c] + bias[col]);
                    atomicAdd(&out[(size_t)s_tok[row] * DOUT + n0 + col], v);
                }
            }
            __syncwarp();
        }
    }
}

// ---------------- launch -------------------------------------------------
extern "C" void kernel_launch(void* const* d_in, const int* in_sizes, int n_in,
                              void* d_out, int out_size) {
    const float* x  = (const float*)d_in[0];   // [16384, 512]
    const float* gw = (const float*)d_in[1];   // [512, 16]
    const float* gb = (const float*)d_in[2];   // [16]
    const float* ew = (const float*)d_in[3];   // [16, 512, 512]
    const float* eb = (const float*)d_in[4];   // [16, 512]
    float* out = (float*)d_out;                // [16384, 512]

    void* cnt_ptr = nullptr;
    cudaGetSymbolAddress(&cnt_ptr, g_cnt);
    cudaMemsetAsync(cnt_ptr, 0, NEXP * sizeof(int));

    prep_kernel<<<1280, 256>>>(x, ew, gw, gb, out);

    cudaFuncSetAttribute(moe_gemm_kernel,
                         cudaFuncAttributeMaxDynamicSharedMemorySize, SMEM_BYTES);
    dim3 grid(DOUT / BN, N_TOK / BM, NEXP);    // (4, 128, 16); empty tiles exit early
    moe_gemm_kernel<<<grid, 256, SMEM_BYTES>>>(eb, out);
}